// round 2
// baseline (speedup 1.0000x reference)
#include <cuda_runtime.h>
#include <cstdint>

// SDDMM: out[i] = mask_vals[i] + dot(mat1[rows[i], :], mat2[:, cols[i]])
// Inputs (metadata order): mask_vals f32[1e6], rows int32[1e6], cols int32[1e6],
//                          mat1 f32[8192,128], mat2 f32[128,8192]
// (JAX with x64 disabled downgrades the reference's int64 indices to int32.)
// Output: f32[1e6]

#define NNZ  1000000
#define MDIM 8192
#define NDIM 8192
#define KDIM 128

// Scratch: mat2 transposed to [N, K] so a column becomes a contiguous 512B run.
__device__ float g_mat2T[(size_t)NDIM * KDIM];

// ---------------------------------------------------------------------------
// Transpose mat2 [K=128, N=8192] -> g_mat2T [N, K]
// 32x32 smem tiles, 32x8 threads. Both read and write coalesced.
// ---------------------------------------------------------------------------
__global__ void transpose_k(const float* __restrict__ mat2) {
    __shared__ float tile[32][33];
    const int n0 = blockIdx.x * 32;
    const int k0 = blockIdx.y * 32;
    #pragma unroll
    for (int r = threadIdx.y; r < 32; r += 8)
        tile[r][threadIdx.x] = mat2[(size_t)(k0 + r) * NDIM + n0 + threadIdx.x];
    __syncthreads();
    #pragma unroll
    for (int r = threadIdx.y; r < 32; r += 8)
        g_mat2T[(size_t)(n0 + r) * KDIM + k0 + threadIdx.x] = tile[threadIdx.x][r];
}

// ---------------------------------------------------------------------------
// Warp-per-nnz SDDMM. Each lane: one float4 of the row + one float4 of the
// (transposed) column -> 4 FMAs -> butterfly reduce -> lane 0 stores.
// ---------------------------------------------------------------------------
__global__ void __launch_bounds__(256)
sddmm_k(const float* __restrict__ mask_vals,
        const int* __restrict__ rows,
        const int* __restrict__ cols,
        const float* __restrict__ mat1,
        float* __restrict__ out) {
    const int gtid = blockIdx.x * blockDim.x + threadIdx.x;
    const int i    = gtid >> 5;     // nnz index (one warp per nnz)
    const int lane = gtid & 31;
    if (i >= NNZ) return;

    const int r = rows[i];          // warp-uniform broadcast load
    const int c = cols[i];

    const float4* __restrict__ a4 =
        reinterpret_cast<const float4*>(mat1 + (size_t)r * KDIM);
    const float4* __restrict__ b4 =
        reinterpret_cast<const float4*>(g_mat2T + (size_t)c * KDIM);

    const float4 a = a4[lane];
    const float4 b = b4[lane];

    float s = a.x * b.x;
    s = fmaf(a.y, b.y, s);
    s = fmaf(a.z, b.z, s);
    s = fmaf(a.w, b.w, s);

    #pragma unroll
    for (int o = 16; o > 0; o >>= 1)
        s += __shfl_xor_sync(0xFFFFFFFFu, s, o);

    if (lane == 0)
        out[i] = mask_vals[i] + s;
}

extern "C" void kernel_launch(void* const* d_in, const int* in_sizes, int n_in,
                              void* d_out, int out_size) {
    const float* mask_vals = (const float*)d_in[0];
    const int*   rows      = (const int*)d_in[1];
    const int*   cols      = (const int*)d_in[2];
    const float* mat1      = (const float*)d_in[3];
    const float* mat2      = (const float*)d_in[4];
    float*       out       = (float*)d_out;

    // 1) Transpose mat2 into scratch
    dim3 tgrid(NDIM / 32, KDIM / 32);
    dim3 tblk(32, 8);
    transpose_k<<<tgrid, tblk>>>(mat2);

    // 2) Warp-per-nnz SDDMM: 1e6 warps, 8 warps/block -> 125000 blocks
    const int threads = 256;
    const int warps_per_block = threads / 32;
    const int blocks = (NNZ + warps_per_block - 1) / warps_per_block;
    sddmm_k<<<blocks, threads>>>(mask_vals, rows, cols, mat1, out);
}

// round 3
// speedup vs baseline: 1.0699x; 1.0699x over previous
#include <cuda_runtime.h>
#include <cstdint>

// SDDMM: out[i] = mask_vals[i] + dot(mat1[rows[i], :], mat2[:, cols[i]])
// Inputs: mask_vals f32[1e6], rows i32[1e6], cols i32[1e6],
//         mat1 f32[8192,128], mat2 f32[128,8192]   Output: f32[1e6]

#define NNZ  1000000
#define MDIM 8192
#define NDIM 8192
#define KDIM 128

// Scratch: mat2 transposed to [N, K] so a column is a contiguous 512B run.
__device__ float g_mat2T[(size_t)NDIM * KDIM];

// ---------------------------------------------------------------------------
// Transpose mat2 [K=128, N=8192] -> g_mat2T [N, K]
// ---------------------------------------------------------------------------
__global__ void transpose_k(const float* __restrict__ mat2) {
    __shared__ float tile[32][33];
    const int n0 = blockIdx.x * 32;
    const int k0 = blockIdx.y * 32;
    #pragma unroll
    for (int r = threadIdx.y; r < 32; r += 8)
        tile[r][threadIdx.x] = mat2[(size_t)(k0 + r) * NDIM + n0 + threadIdx.x];
    __syncthreads();
    #pragma unroll
    for (int r = threadIdx.y; r < 32; r += 8)
        g_mat2T[(size_t)(n0 + r) * KDIM + k0 + threadIdx.x] = tile[threadIdx.x][r];
}

// ---------------------------------------------------------------------------
// Grid-stride SDDMM, 4 nnz per warp per iteration (ILP batch).
// Per iter: 2x int4 idx loads, 8x LDG.128 data (MLP=8), 16 FFMA,
// 4 independent butterfly reduces, 1 float4 mask load, 1 STG.128.
// ---------------------------------------------------------------------------
__global__ void __launch_bounds__(256)
sddmm_k(const float* __restrict__ mask_vals,
        const int* __restrict__ rows,
        const int* __restrict__ cols,
        const float* __restrict__ mat1,
        float* __restrict__ out) {
    const int lane    = threadIdx.x & 31;
    const int gwarp   = (blockIdx.x * blockDim.x + threadIdx.x) >> 5;
    const int nwarps  = (gridDim.x * blockDim.x) >> 5;

    for (int base = gwarp * 4; base < NNZ; base += nwarps * 4) {
        // Warp-uniform vector index loads (NNZ % 4 == 0, base 16B-aligned)
        const int4 ri = *reinterpret_cast<const int4*>(rows + base);
        const int4 ci = *reinterpret_cast<const int4*>(cols + base);

        const float4* __restrict__ a0p = reinterpret_cast<const float4*>(mat1    + (size_t)ri.x * KDIM);
        const float4* __restrict__ b0p = reinterpret_cast<const float4*>(g_mat2T + (size_t)ci.x * KDIM);
        const float4* __restrict__ a1p = reinterpret_cast<const float4*>(mat1    + (size_t)ri.y * KDIM);
        const float4* __restrict__ b1p = reinterpret_cast<const float4*>(g_mat2T + (size_t)ci.y * KDIM);
        const float4* __restrict__ a2p = reinterpret_cast<const float4*>(mat1    + (size_t)ri.z * KDIM);
        const float4* __restrict__ b2p = reinterpret_cast<const float4*>(g_mat2T + (size_t)ci.z * KDIM);
        const float4* __restrict__ a3p = reinterpret_cast<const float4*>(mat1    + (size_t)ri.w * KDIM);
        const float4* __restrict__ b3p = reinterpret_cast<const float4*>(g_mat2T + (size_t)ci.w * KDIM);

        // Issue all 8 loads back-to-back (MLP=8)
        const float4 a0 = a0p[lane];
        const float4 b0 = b0p[lane];
        const float4 a1 = a1p[lane];
        const float4 b1 = b1p[lane];
        const float4 a2 = a2p[lane];
        const float4 b2 = b2p[lane];
        const float4 a3 = a3p[lane];
        const float4 b3 = b3p[lane];

        float s0 = a0.x * b0.x; s0 = fmaf(a0.y, b0.y, s0); s0 = fmaf(a0.z, b0.z, s0); s0 = fmaf(a0.w, b0.w, s0);
        float s1 = a1.x * b1.x; s1 = fmaf(a1.y, b1.y, s1); s1 = fmaf(a1.z, b1.z, s1); s1 = fmaf(a1.w, b1.w, s1);
        float s2 = a2.x * b2.x; s2 = fmaf(a2.y, b2.y, s2); s2 = fmaf(a2.z, b2.z, s2); s2 = fmaf(a2.w, b2.w, s2);
        float s3 = a3.x * b3.x; s3 = fmaf(a3.y, b3.y, s3); s3 = fmaf(a3.z, b3.z, s3); s3 = fmaf(a3.w, b3.w, s3);

        // 4 independent butterfly reductions (pipelined by the scheduler)
        #pragma unroll
        for (int o = 16; o > 0; o >>= 1) {
            s0 += __shfl_xor_sync(0xFFFFFFFFu, s0, o);
            s1 += __shfl_xor_sync(0xFFFFFFFFu, s1, o);
            s2 += __shfl_xor_sync(0xFFFFFFFFu, s2, o);
            s3 += __shfl_xor_sync(0xFFFFFFFFu, s3, o);
        }

        if (lane == 0) {
            const float4 mv = *reinterpret_cast<const float4*>(mask_vals + base);
            float4 o4;
            o4.x = mv.x + s0;
            o4.y = mv.y + s1;
            o4.z = mv.z + s2;
            o4.w = mv.w + s3;
            *reinterpret_cast<float4*>(out + base) = o4;
        }
    }
}

extern "C" void kernel_launch(void* const* d_in, const int* in_sizes, int n_in,
                              void* d_out, int out_size) {
    const float* mask_vals = (const float*)d_in[0];
    const int*   rows      = (const int*)d_in[1];
    const int*   cols      = (const int*)d_in[2];
    const float* mat1      = (const float*)d_in[3];
    const float* mat2      = (const float*)d_in[4];
    float*       out       = (float*)d_out;

    dim3 tgrid(NDIM / 32, KDIM / 32);
    dim3 tblk(32, 8);
    transpose_k<<<tgrid, tblk>>>(mat2);

    // Persistent-ish grid: 8 blocks/SM x 148 SMs
    const int blocks = 148 * 8;
    sddmm_k<<<blocks, 256>>>(mask_vals, rows, cols, mat1, out);
}

// round 4
// speedup vs baseline: 1.4265x; 1.3333x over previous
#include <cuda_runtime.h>
#include <cstdint>

// SDDMM: out[i] = mask_vals[i] + dot(mat1[rows[i], :], mat2[:, cols[i]])
// Inputs: mask_vals f32[1e6], rows i32[1e6], cols i32[1e6],
//         mat1 f32[8192,128], mat2 f32[128,8192]   Output: f32[1e6]

#define NNZ  1000000
#define MDIM 8192
#define NDIM 8192
#define KDIM 128

// Scratch: mat2 transposed to [N, K] so a column is a contiguous 512B run.
__device__ float g_mat2T[(size_t)NDIM * KDIM];

// ---------------------------------------------------------------------------
// Transpose mat2 [K=128, N=8192] -> g_mat2T [N, K]
// ---------------------------------------------------------------------------
__global__ void transpose_k(const float* __restrict__ mat2) {
    __shared__ float tile[32][33];
    const int n0 = blockIdx.x * 32;
    const int k0 = blockIdx.y * 32;
    #pragma unroll
    for (int r = threadIdx.y; r < 32; r += 8)
        tile[r][threadIdx.x] = mat2[(size_t)(k0 + r) * NDIM + n0 + threadIdx.x];
    __syncthreads();
    #pragma unroll
    for (int r = threadIdx.y; r < 32; r += 8)
        g_mat2T[(size_t)(n0 + r) * KDIM + k0 + threadIdx.x] = tile[threadIdx.x][r];
}

// ---------------------------------------------------------------------------
// Grid-stride SDDMM: 8 lanes per nnz, 4 nnz per warp-iteration.
// Lane layout: grp = lane>>3 selects which nnz, sub = lane&7 selects the
// 16B chunk. Each lane: 4 float4 from the row + 4 from the column
// (chunks sub, sub+8, sub+16, sub+24) -> 16 FMA -> 3-step 8-lane butterfly.
// Per iter warp-wide: 8 LDG.128 (32 wavefronts, MLP=8) + only 3 SHFLs.
// ---------------------------------------------------------------------------
__global__ void __launch_bounds__(256)
sddmm_k(const float* __restrict__ mask_vals,
        const int* __restrict__ rows,
        const int* __restrict__ cols,
        const float* __restrict__ mat1,
        float* __restrict__ out) {
    const int lane   = threadIdx.x & 31;
    const int sub    = lane & 7;    // chunk index within the nnz
    const int grp    = lane >> 3;   // which of the 4 nnz this lane works on
    const int gwarp  = (blockIdx.x * blockDim.x + threadIdx.x) >> 5;
    const int nwarps = (gridDim.x * blockDim.x) >> 5;

    for (int base = gwarp * 4; base < NNZ; base += nwarps * 4) {
        const int i = base + grp;           // this group's nnz
        const int r = rows[i];              // 4 distinct 4B addrs -> 1 sector
        const int c = cols[i];

        const float4* __restrict__ a4 =
            reinterpret_cast<const float4*>(mat1 + (size_t)r * KDIM);
        const float4* __restrict__ b4 =
            reinterpret_cast<const float4*>(g_mat2T + (size_t)c * KDIM);

        // 8 independent LDG.128 (each instr: 4 groups x contiguous 128B)
        const float4 a0 = a4[sub];
        const float4 b0 = b4[sub];
        const float4 a1 = a4[sub + 8];
        const float4 b1 = b4[sub + 8];
        const float4 a2 = a4[sub + 16];
        const float4 b2 = b4[sub + 16];
        const float4 a3 = a4[sub + 24];
        const float4 b3 = b4[sub + 24];

        float s = a0.x * b0.x;
        s = fmaf(a0.y, b0.y, s); s = fmaf(a0.z, b0.z, s); s = fmaf(a0.w, b0.w, s);
        s = fmaf(a1.x, b1.x, s); s = fmaf(a1.y, b1.y, s);
        s = fmaf(a1.z, b1.z, s); s = fmaf(a1.w, b1.w, s);
        s = fmaf(a2.x, b2.x, s); s = fmaf(a2.y, b2.y, s);
        s = fmaf(a2.z, b2.z, s); s = fmaf(a2.w, b2.w, s);
        s = fmaf(a3.x, b3.x, s); s = fmaf(a3.y, b3.y, s);
        s = fmaf(a3.z, b3.z, s); s = fmaf(a3.w, b3.w, s);

        // Reduce within the 8-lane group (offsets stay inside the group)
        s += __shfl_xor_sync(0xFFFFFFFFu, s, 4);
        s += __shfl_xor_sync(0xFFFFFFFFu, s, 2);
        s += __shfl_xor_sync(0xFFFFFFFFu, s, 1);

        if (sub == 0)                       // lanes 0,8,16,24: 16B span
            out[i] = mask_vals[i] + s;
    }
}

extern "C" void kernel_launch(void* const* d_in, const int* in_sizes, int n_in,
                              void* d_out, int out_size) {
    const float* mask_vals = (const float*)d_in[0];
    const int*   rows      = (const int*)d_in[1];
    const int*   cols      = (const int*)d_in[2];
    const float* mat1      = (const float*)d_in[3];
    const float* mat2      = (const float*)d_in[4];
    float*       out       = (float*)d_out;

    dim3 tgrid(NDIM / 32, KDIM / 32);
    dim3 tblk(32, 8);
    transpose_k<<<tgrid, tblk>>>(mat2);

    const int blocks = 148 * 8;
    sddmm_k<<<blocks, 256>>>(mask_vals, rows, cols, mat1, out);
}